// round 4
// baseline (speedup 1.0000x reference)
#include <cuda_runtime.h>
#include <cuda_bf16.h>

// mean_{i,j}(x[j]-x[i])^2 == 2*E[x^2] - 2*(E[x])^2
// N = 16384 floats (64 KB). Multi-block two-moment reduction:
// 16 blocks x 256 threads, one float4 per thread (single wave across SMs),
// atomic combine + last-block finalize/reset (graph-replay safe).

#define NBLOCKS  16
#define NTHREADS 256

__device__ float        g_sum   = 0.0f;
__device__ float        g_sum2  = 0.0f;
__device__ unsigned int g_count = 0u;

__global__ __launch_bounds__(NTHREADS, 1)
void EditLoss_55525337203377_kernel(const float* __restrict__ x, float* __restrict__ out, int n) {
    const int tid = threadIdx.x;
    const int idx = blockIdx.x * NTHREADS + tid;
    const float4* x4 = reinterpret_cast<const float4*>(x);
    const int n4 = n >> 2;

    float s = 0.0f, s2 = 0.0f;
    // Exactly one iteration for n=16384 with 16x256; loop keeps it general.
    for (int i = idx; i < n4; i += NBLOCKS * NTHREADS) {
        float4 v = x4[i];
        s  += v.x + v.y + v.z + v.w;
        s2 += v.x * v.x + v.y * v.y + v.z * v.z + v.w * v.w;
    }

    // intra-warp reduce
    #pragma unroll
    for (int off = 16; off > 0; off >>= 1) {
        s  += __shfl_xor_sync(0xFFFFFFFFu, s,  off);
        s2 += __shfl_xor_sync(0xFFFFFFFFu, s2, off);
    }

    __shared__ float sh_s[NTHREADS / 32];
    __shared__ float sh_s2[NTHREADS / 32];
    const int wid = tid >> 5;
    const int lid = tid & 31;
    if (lid == 0) { sh_s[wid] = s; sh_s2[wid] = s2; }
    __syncthreads();

    if (wid == 0) {
        const int nw = NTHREADS / 32;  // 8
        float a  = (lid < nw) ? sh_s[lid]  : 0.0f;
        float a2 = (lid < nw) ? sh_s2[lid] : 0.0f;
        #pragma unroll
        for (int off = 4; off > 0; off >>= 1) {
            a  += __shfl_xor_sync(0xFFFFFFFFu, a,  off);
            a2 += __shfl_xor_sync(0xFFFFFFFFu, a2, off);
        }
        if (lid == 0) {
            atomicAdd(&g_sum,  a);
            atomicAdd(&g_sum2, a2);
            __threadfence();
            unsigned int ticket = atomicAdd(&g_count, 1u);
            if (ticket == (unsigned int)(gridDim.x - 1)) {
                // All blocks' partials are globally visible (each fenced before
                // its counter increment). Read totals via L2 atomics to bypass
                // any stale L1 line.
                float sv  = atomicAdd(&g_sum,  0.0f);
                float s2v = atomicAdd(&g_sum2, 0.0f);
                float inv_n = 1.0f / (float)n;
                float mean  = sv  * inv_n;
                float m2    = s2v * inv_n;
                out[0] = 2.0f * (m2 - mean * mean);
                // Reset for the next (graph-replayed) launch. Cross-launch
                // visibility is guaranteed by kernel-completion ordering;
                // the fence orders the zeroing before the counter release.
                g_sum  = 0.0f;
                g_sum2 = 0.0f;
                __threadfence();
                g_count = 0u;
            }
        }
    }
}

extern "C" void kernel_launch(void* const* d_in, const int* in_sizes, int n_in,
                              void* d_out, int out_size) {
    const float* x = (const float*)d_in[0];
    float* out = (float*)d_out;
    int n = in_sizes[0];
    EditLoss_55525337203377_kernel<<<NBLOCKS, NTHREADS>>>(x, out, n);
}

// round 6
// speedup vs baseline: 1.2462x; 1.2462x over previous
#include <cuda_runtime.h>
#include <cuda_bf16.h>

// mean_{i,j}(x[j]-x[i])^2 == 2*E[x^2] - 2*(E[x])^2
// N = 16384 floats (64 KB). Single-block two-moment reduction.
// 1024 threads x 4 front-batched float4 loads (max MLP), shfl butterfly
// reductions (two independent chains interleave), one smem stage.

#define NTHREADS 1024

__device__ __forceinline__ void warp_sum2(float& s, float& s2) {
    #pragma unroll
    for (int off = 16; off > 0; off >>= 1) {
        s  += __shfl_xor_sync(0xFFFFFFFFu, s,  off);
        s2 += __shfl_xor_sync(0xFFFFFFFFu, s2, off);
    }
}

__global__ __launch_bounds__(NTHREADS, 1)
void EditLoss_55525337203377_kernel(const float* __restrict__ x, float* __restrict__ out, int n) {
    const int tid = threadIdx.x;
    const float4* x4 = reinterpret_cast<const float4*>(x);
    // n = 16384 -> 4096 float4 -> exactly 4 per thread at 1024 threads.

    // Front-batch all 4 loads (independent => one exposed memory latency).
    float4 a = x4[tid];
    float4 b = x4[tid + NTHREADS];
    float4 c = x4[tid + 2 * NTHREADS];
    float4 d = x4[tid + 3 * NTHREADS];

    float s  = (a.x + a.y) + (a.z + a.w)
             + (b.x + b.y) + (b.z + b.w)
             + (c.x + c.y) + (c.z + c.w)
             + (d.x + d.y) + (d.z + d.w);

    float s2 = a.x * a.x;
    s2 = fmaf(a.y, a.y, s2); s2 = fmaf(a.z, a.z, s2); s2 = fmaf(a.w, a.w, s2);
    s2 = fmaf(b.x, b.x, s2); s2 = fmaf(b.y, b.y, s2); s2 = fmaf(b.z, b.z, s2); s2 = fmaf(b.w, b.w, s2);
    s2 = fmaf(c.x, c.x, s2); s2 = fmaf(c.y, c.y, s2); s2 = fmaf(c.z, c.z, s2); s2 = fmaf(c.w, c.w, s2);
    s2 = fmaf(d.x, d.x, s2); s2 = fmaf(d.y, d.y, s2); s2 = fmaf(d.z, d.z, s2); s2 = fmaf(d.w, d.w, s2);

    warp_sum2(s, s2);

    __shared__ float sh_s[NTHREADS / 32];   // 32 warps
    __shared__ float sh_s2[NTHREADS / 32];
    const int wid = tid >> 5;
    const int lid = tid & 31;
    if (lid == 0) { sh_s[wid] = s; sh_s2[wid] = s2; }
    __syncthreads();

    if (wid == 0) {
        float a1 = sh_s[lid];    // exactly 32 partials, one per lane
        float a2 = sh_s2[lid];
        warp_sum2(a1, a2);
        if (lid == 0) {
            // n is always 16384; 1/16384 is an exact power of two.
            const float inv_n = 6.103515625e-5f;
            float mean = a1 * inv_n;
            float m2   = a2 * inv_n;
            out[0] = 2.0f * fmaf(-mean, mean, m2);
        }
    }
}

extern "C" void kernel_launch(void* const* d_in, const int* in_sizes, int n_in,
                              void* d_out, int out_size) {
    const float* x = (const float*)d_in[0];
    float* out = (float*)d_out;
    int n = in_sizes[0];
    EditLoss_55525337203377_kernel<<<1, NTHREADS>>>(x, out, n);
}

// round 7
// speedup vs baseline: 1.2591x; 1.0104x over previous
#include <cuda_runtime.h>
#include <cuda_bf16.h>

// mean_{i,j}(x[j]-x[i])^2 == 2*E[x^2] - 2*(E[x])^2
// N = 16384 floats (64 KB). Single-block two-moment reduction.
// 512 threads x 8 front-batched float4 loads (explicit MLP=8/thread),
// interleaved shfl butterfly reductions, one smem stage (16 partials).

#define NTHREADS 512

__device__ __forceinline__ void warp_sum2(float& s, float& s2) {
    #pragma unroll
    for (int off = 16; off > 0; off >>= 1) {
        s  += __shfl_xor_sync(0xFFFFFFFFu, s,  off);
        s2 += __shfl_xor_sync(0xFFFFFFFFu, s2, off);
    }
}

__global__ __launch_bounds__(NTHREADS, 1)
void EditLoss_55525337203377_kernel(const float* __restrict__ x, float* __restrict__ out, int n) {
    const int tid = threadIdx.x;
    const float4* x4 = reinterpret_cast<const float4*>(x);
    // n = 16384 -> 4096 float4 -> exactly 8 per thread at 512 threads.

    // Front-batch all 8 loads: fully independent, one exposed memory latency.
    float4 v[8];
    #pragma unroll
    for (int i = 0; i < 8; i++)
        v[i] = x4[tid + i * NTHREADS];

    float s = 0.0f, s2 = 0.0f;
    #pragma unroll
    for (int i = 0; i < 8; i++) {
        s += (v[i].x + v[i].y) + (v[i].z + v[i].w);
        s2 = fmaf(v[i].x, v[i].x, s2);
        s2 = fmaf(v[i].y, v[i].y, s2);
        s2 = fmaf(v[i].z, v[i].z, s2);
        s2 = fmaf(v[i].w, v[i].w, s2);
    }

    warp_sum2(s, s2);

    __shared__ float sh_s[NTHREADS / 32];   // 16 warps
    __shared__ float sh_s2[NTHREADS / 32];
    const int wid = tid >> 5;
    const int lid = tid & 31;
    if (lid == 0) { sh_s[wid] = s; sh_s2[wid] = s2; }
    __syncthreads();

    if (wid == 0) {
        const int nw = NTHREADS / 32;  // 16
        float a1 = (lid < nw) ? sh_s[lid]  : 0.0f;
        float a2 = (lid < nw) ? sh_s2[lid] : 0.0f;
        #pragma unroll
        for (int off = 8; off > 0; off >>= 1) {
            a1 += __shfl_xor_sync(0xFFFFFFFFu, a1, off);
            a2 += __shfl_xor_sync(0xFFFFFFFFu, a2, off);
        }
        if (lid == 0) {
            // n is always 16384; 1/16384 is an exact power of two.
            const float inv_n = 6.103515625e-5f;
            float mean = a1 * inv_n;
            float m2   = a2 * inv_n;
            out[0] = 2.0f * fmaf(-mean, mean, m2);
        }
    }
}

extern "C" void kernel_launch(void* const* d_in, const int* in_sizes, int n_in,
                              void* d_out, int out_size) {
    const float* x = (const float*)d_in[0];
    float* out = (float*)d_out;
    int n = in_sizes[0];
    EditLoss_55525337203377_kernel<<<1, NTHREADS>>>(x, out, n);
}